// round 2
// baseline (speedup 1.0000x reference)
#include <cuda_runtime.h>
#include <cuda_bf16.h>

// Problem constants
#define B_   16
#define C_   64
#define H_   256
#define W_   256
#define HW_  (H_ * W_)            // 65536
#define BHW_ (B_ * HW_)           // 1048576
#define K_   11
#define P_   5
#define EPS_ 1e-6f

// Scratch: 3 maps (sxx, sxy, syy) before and after horizontal blur.
// 12 MiB each — __device__ globals (no allocation allowed in kernel_launch).
__device__ float d_S[3 * BHW_];
__device__ float d_T[3 * BHW_];

// ---------------------------------------------------------------------------
// Kernel 1: channel reduction. Each thread owns 4 consecutive w-pixels (float4),
// loops over C=64 channels with stride HW. Fully coalesced; unrolled for MLP.
// Reads 512 MiB — this kernel is the HBM roofline term.
// ---------------------------------------------------------------------------
__global__ void k_reduce(const float4* __restrict__ x, const float4* __restrict__ y) {
    int idx = blockIdx.x * blockDim.x + threadIdx.x;   // 0 .. B*HW/4-1 = 262143
    int b = idx >> 14;                                  // HW/4 = 16384
    int p = idx & 16383;

    const float4* xp = x + (size_t)b * (C_ * (HW_ / 4)) + p;
    const float4* yp = y + (size_t)b * (C_ * (HW_ / 4)) + p;

    float4 axx = make_float4(0.f, 0.f, 0.f, 0.f);
    float4 axy = make_float4(0.f, 0.f, 0.f, 0.f);
    float4 ayy = make_float4(0.f, 0.f, 0.f, 0.f);

#pragma unroll 8
    for (int c = 0; c < C_; c++) {
        float4 xv = xp[c * (HW_ / 4)];
        float4 yv = yp[c * (HW_ / 4)];
        axx.x += xv.x * xv.x; axx.y += xv.y * xv.y; axx.z += xv.z * xv.z; axx.w += xv.w * xv.w;
        axy.x += xv.x * yv.x; axy.y += xv.y * yv.y; axy.z += xv.z * yv.z; axy.w += xv.w * yv.w;
        ayy.x += yv.x * yv.x; ayy.y += yv.y * yv.y; ayy.z += yv.z * yv.z; ayy.w += yv.w * yv.w;
    }

    float4* S4 = reinterpret_cast<float4*>(d_S);
    int out4 = b * (HW_ / 4) + p;
    S4[out4]                   = axx;
    S4[out4 + BHW_ / 4]        = axy;
    S4[out4 + 2 * (BHW_ / 4)]  = ayy;
}

// ---------------------------------------------------------------------------
// Kernel 2: horizontal 11-tap blur along w (zero padding), all 3 maps at once
// (map index folded into the linear index). Data is L2-resident (12 MiB).
// 1D factor recovered from the separable 2D gaussian:
//   g1[i] = gauss[5][i] * rsqrt(gauss[5][5])   (exact since g = g1 (x) g1)
// ---------------------------------------------------------------------------
__global__ void k_hblur(const float* __restrict__ gauss) {
    __shared__ float g1[K_];
    if (threadIdx.x < K_)
        g1[threadIdx.x] = gauss[5 * K_ + threadIdx.x] * rsqrtf(gauss[5 * K_ + 5]);
    __syncthreads();

    int idx = blockIdx.x * blockDim.x + threadIdx.x;   // 0 .. 3*BHW-1
    if (idx >= 3 * BHW_) return;
    int w       = idx & (W_ - 1);
    int rowbase = idx & ~(W_ - 1);

    float acc = 0.f;
#pragma unroll
    for (int k = 0; k < K_; k++) {
        int ww = w + k - P_;
        if ((unsigned)ww < (unsigned)W_)
            acc += g1[k] * d_S[rowbase + ww];
    }
    d_T[idx] = acc;
}

// ---------------------------------------------------------------------------
// Kernel 3: vertical 11-tap blur along h (zero padding) for all 3 maps,
// fused with the cosine-similarity combine. Stride-W loads are coalesced
// across threads (adjacent threads -> adjacent w).
// ---------------------------------------------------------------------------
__global__ void k_vblur(const float* __restrict__ gauss, float* __restrict__ out) {
    __shared__ float g1[K_];
    if (threadIdx.x < K_)
        g1[threadIdx.x] = gauss[5 * K_ + threadIdx.x] * rsqrtf(gauss[5 * K_ + 5]);
    __syncthreads();

    int idx = blockIdx.x * blockDim.x + threadIdx.x;   // 0 .. BHW-1
    if (idx >= BHW_) return;
    int w = idx & (W_ - 1);
    int h = (idx >> 8) & (H_ - 1);
    int b = idx >> 16;

    int base = b * HW_ + w;
    float sxx = 0.f, sxy = 0.f, syy = 0.f;
#pragma unroll
    for (int k = 0; k < K_; k++) {
        int hh = h + k - P_;
        if ((unsigned)hh < (unsigned)H_) {
            float g   = g1[k];
            int  off  = base + hh * W_;
            sxx += g * d_T[off];
            sxy += g * d_T[off + BHW_];
            syy += g * d_T[off + 2 * BHW_];
        }
    }
    out[idx] = sxy / (sqrtf(sxx) * sqrtf(syy) + EPS_);
}

// ---------------------------------------------------------------------------
extern "C" void kernel_launch(void* const* d_in, const int* in_sizes, int n_in,
                              void* d_out, int out_size) {
    const float4* x     = (const float4*)d_in[0];
    const float4* y     = (const float4*)d_in[1];
    const float*  gauss = (const float*)d_in[2];
    float*        out   = (float*)d_out;

    k_reduce<<<(B_ * HW_ / 4 + 255) / 256, 256>>>(x, y);
    k_hblur<<<(3 * BHW_ + 255) / 256, 256>>>(gauss);
    k_vblur<<<(BHW_ + 255) / 256, 256>>>(gauss, out);
}